// round 12
// baseline (speedup 1.0000x reference)
#include <cuda_runtime.h>
#include <cuda_bf16.h>
#include <cstdint>

#define N4K 4096

// ---------------- device scratch (allocation-free) ----------------
__device__ __nv_bfloat16 g_Ahi[(size_t)N4K * N4K];
__device__ __nv_bfloat16 g_Alo[(size_t)N4K * N4K];
__device__ __nv_bfloat16 g_Bhi[(size_t)N4K * N4K];   // transposed: [N, K]
__device__ __nv_bfloat16 g_Blo[(size_t)N4K * N4K];   // transposed: [N, K]

// ---------------- helpers ----------------
__device__ __forceinline__ uint32_t smem_u32(const void* p) {
    uint32_t a;
    asm("{ .reg .u64 t; cvta.to.shared.u64 t, %1; cvt.u32.u64 %0, t; }"
        : "=r"(a) : "l"(p));
    return a;
}

__device__ __forceinline__ void ldsm4(uint32_t* r, uint32_t addr) {
    asm volatile("ldmatrix.sync.aligned.m8n8.x4.shared.b16 {%0,%1,%2,%3}, [%4];"
        : "=r"(r[0]), "=r"(r[1]), "=r"(r[2]), "=r"(r[3]) : "r"(addr));
}

__device__ __forceinline__ void mma16816(float* c, const uint32_t* a,
                                         uint32_t b0, uint32_t b1) {
    asm volatile(
        "mma.sync.aligned.m16n8k16.row.col.f32.bf16.bf16.f32 "
        "{%0,%1,%2,%3},{%4,%5,%6,%7},{%8,%9},{%0,%1,%2,%3};"
        : "+f"(c[0]), "+f"(c[1]), "+f"(c[2]), "+f"(c[3])
        : "r"(a[0]), "r"(a[1]), "r"(a[2]), "r"(a[3]), "r"(b0), "r"(b1));
}

__device__ __forceinline__ void cpasync16(uint32_t saddr, const void* g) {
    asm volatile("cp.async.cg.shared.global [%0], [%1], 16;"
        :: "r"(saddr), "l"(g));
}

// ---------------- conversion kernels ----------------
__global__ void __launch_bounds__(256) conv_a(const float* __restrict__ A) {
    size_t t = (size_t)blockIdx.x * 256 + threadIdx.x;   // float4 index
    int i  = (int)(t >> 10);          // row
    int c4 = (int)(t & 1023) << 2;    // col start
    float4 v = *reinterpret_cast<const float4*>(A + (size_t)i * N4K + c4);
    float a0 = (c4 + 0 <= i) ? v.x : 0.0f;
    float a1 = (c4 + 1 <= i) ? v.y : 0.0f;
    float a2 = (c4 + 2 <= i) ? v.z : 0.0f;
    float a3 = (c4 + 3 <= i) ? v.w : 0.0f;
    __nv_bfloat16 h0 = __float2bfloat16(a0), h1 = __float2bfloat16(a1);
    __nv_bfloat16 h2 = __float2bfloat16(a2), h3 = __float2bfloat16(a3);
    __nv_bfloat16 l0 = __float2bfloat16(a0 - __bfloat162float(h0));
    __nv_bfloat16 l1 = __float2bfloat16(a1 - __bfloat162float(h1));
    __nv_bfloat16 l2 = __float2bfloat16(a2 - __bfloat162float(h2));
    __nv_bfloat16 l3 = __float2bfloat16(a3 - __bfloat162float(h3));
    uint2 uh, ul;
    uh.x = (uint32_t)__bfloat16_as_ushort(h0) | ((uint32_t)__bfloat16_as_ushort(h1) << 16);
    uh.y = (uint32_t)__bfloat16_as_ushort(h2) | ((uint32_t)__bfloat16_as_ushort(h3) << 16);
    ul.x = (uint32_t)__bfloat16_as_ushort(l0) | ((uint32_t)__bfloat16_as_ushort(l1) << 16);
    ul.y = (uint32_t)__bfloat16_as_ushort(l2) | ((uint32_t)__bfloat16_as_ushort(l3) << 16);
    *reinterpret_cast<uint2*>(&g_Ahi[(size_t)i * N4K + c4]) = uh;
    *reinterpret_cast<uint2*>(&g_Alo[(size_t)i * N4K + c4]) = ul;
}

// B: transpose + mask(tril: keep k >= j) -> Bt[j][k]
__global__ void __launch_bounds__(256) conv_b(const float* __restrict__ B) {
    __shared__ float tile[32][33];
    int j0 = blockIdx.x * 32, k0 = blockIdx.y * 32;
    int tx = threadIdx.x & 31, ty = threadIdx.x >> 5;   // ty 0..7
#pragma unroll
    for (int yy = 0; yy < 4; yy++) {
        int k = k0 + ty + yy * 8;
        int j = j0 + tx;
        float v = B[(size_t)k * N4K + j];
        if (k < j) v = 0.0f;
        tile[ty + yy * 8][tx] = v;
    }
    __syncthreads();
#pragma unroll
    for (int yy = 0; yy < 4; yy++) {
        int j = j0 + ty + yy * 8;
        int k = k0 + tx;
        float v = tile[tx][ty + yy * 8];
        __nv_bfloat16 hi = __float2bfloat16(v);
        __nv_bfloat16 lo = __float2bfloat16(v - __bfloat162float(hi));
        g_Bhi[(size_t)j * N4K + k] = hi;
        g_Blo[(size_t)j * N4K + k] = lo;
    }
}

// ---------------- zero upper triangle tiles (128x128 granularity) ----------------
__global__ void __launch_bounds__(256) zero_upper(float* __restrict__ C) {
    int bj = blockIdx.x, bi = blockIdx.y;
    if (bi >= bj) return;
    int rowBase = bi * 128, colBase = bj * 128;
    float4 z = make_float4(0.f, 0.f, 0.f, 0.f);
#pragma unroll
    for (int it = 0; it < 16; it++) {
        int idx = threadIdx.x + it * 256;       // float4 index in 128x32
        int r = idx >> 5, c4 = (idx & 31) << 2;
        *reinterpret_cast<float4*>(&C[(size_t)(rowBase + r) * N4K + colBase + c4]) = z;
    }
}

// ---------------- main warp-MMA GEMM: CTA 128x256, warp 64x64, 3-stage ----------
// SMEM per stage: A tile 128 rows x 128B (hi|lo interleaved, SW128) = 16KB
//                 B tile 256 rows x 128B = 32KB ;  stage = 48KB, 3 stages = 144KB
#define A_TILE_BYTES 16384
#define B_OFF        16384
#define STAGE_B      49152
#define SMEM_SZ      (3 * STAGE_B)      // 147456

__device__ __forceinline__ void load_stage(uint32_t sbase, int buf, int k0,
                                           int rowBase, int colBase, int tid,
                                           bool valid) {
    if (valid) {
        const uint32_t sb = sbase + buf * STAGE_B;
        // A: 128 rows x 8 chunks(16B). thread t -> row t>>1, grp (t&1): hi(0)/lo(1)
        {
            int r = tid >> 1, grp = tid & 1;
            const __nv_bfloat16* src = grp ? g_Alo : g_Ahi;
            const __nv_bfloat16* pa = src + (size_t)(rowBase + r) * N4K + k0;
            uint32_t dst = sb + (uint32_t)(r * 128);
            uint32_t xm = (uint32_t)((r & 7) << 4);
            uint32_t cb = (uint32_t)(grp * 64);
#pragma unroll
            for (int i = 0; i < 4; i++)
                cpasync16(dst + ((cb + i * 16) ^ xm), pa + i * 8);
        }
        // B: 256 rows x 8 chunks. thread t -> row t, chunks 0..7 (hi 0-3, lo 4-7)
        {
            int r = tid;
            const __nv_bfloat16* ph = g_Bhi + (size_t)(colBase + r) * N4K + k0;
            const __nv_bfloat16* pl = g_Blo + (size_t)(colBase + r) * N4K + k0;
            uint32_t dst = sb + B_OFF + (uint32_t)(r * 128);
            uint32_t xm = (uint32_t)((r & 7) << 4);
#pragma unroll
            for (int i = 0; i < 4; i++)
                cpasync16(dst + (((uint32_t)(i * 16)) ^ xm), ph + i * 8);
#pragma unroll
            for (int i = 0; i < 4; i++)
                cpasync16(dst + (((uint32_t)(64 + i * 16)) ^ xm), pl + i * 8);
        }
    }
    asm volatile("cp.async.commit_group;" ::: "memory");
}

__global__ void __launch_bounds__(256, 1)
trilmm_mma2(float* __restrict__ C) {
    extern __shared__ char smem[];
    const uint32_t sbase = smem_u32(smem);
    const int tid  = threadIdx.x;
    const int wid  = tid >> 5;
    const int lane = tid & 31;
    const int wr = wid >> 2;            // 0..1  -> m offset wr*64
    const int wc = wid & 3;             // 0..3  -> n offset wc*64

    // block mapping: 128x256 lower tiles, largest d2 (most K work) first
    int rem = blockIdx.x, d2 = 31, cnt = 1;
    while (rem >= cnt) { rem -= cnt; d2--; cnt = (31 - d2) / 2 + 1; }
    const int bj2 = rem;
    const int bi  = 2 * bj2 + d2;
    const int rowBase = bi * 128, colBase = bj2 * 256;
    const int nStages = (d2 + 1) * 4;   // K chunks of 32

    float acc[4][8][4];
#pragma unroll
    for (int i = 0; i < 4; i++)
#pragma unroll
        for (int j = 0; j < 8; j++)
#pragma unroll
            for (int k = 0; k < 4; k++) acc[i][j][k] = 0.0f;

    // lane-invariant ldmatrix address parts
    const uint32_t xm  = (uint32_t)((lane & 7) << 4);              // swizzle mask
    const uint32_t pAo = (uint32_t)((wr * 64 + (lane & 15)) * 128);
    const uint32_t l16 = (uint32_t)((lane >> 4) * 16);
    const uint32_t pBo = (uint32_t)((wc * 64 + ((lane >> 4) & 1) * 8 + (lane & 7)) * 128);
    const uint32_t lb  = (uint32_t)((lane & 8) * 2);

    // prologue: 2 stages in flight
    load_stage(sbase, 0, colBase + 0,  rowBase, colBase, tid, true);
    load_stage(sbase, 1, colBase + 32, rowBase, colBase, tid, true);

    int buf = 0;
    for (int s = 0; s < nStages; s++) {
        load_stage(sbase, (s + 2) % 3, colBase + (s + 2) * 32,
                   rowBase, colBase, tid, (s + 2) < nStages);
        asm volatile("cp.async.wait_group 2;" ::: "memory");
        __syncthreads();

        const uint32_t stA = sbase + buf * STAGE_B;
        const uint32_t stB = stA + B_OFF;

#pragma unroll
        for (int ks = 0; ks < 2; ks++) {
            const uint32_t kc = (uint32_t)(ks * 32);
            uint32_t bh[4][4], bl[4][4];
#pragma unroll
            for (int ng = 0; ng < 4; ng++) {
                ldsm4(bh[ng], stB + pBo + ng * 2048 + ((kc + lb) ^ xm));
                ldsm4(bl[ng], stB + pBo + ng * 2048 + ((64 + kc + lb) ^ xm));
            }
#pragma unroll
            for (int mf = 0; mf < 4; mf++) {
                uint32_t ah[4], al[4];
                ldsm4(ah, stA + pAo + mf * 2048 + ((kc + l16) ^ xm));
                ldsm4(al, stA + pAo + mf * 2048 + ((64 + kc + l16) ^ xm));
#pragma unroll
                for (int nf = 0; nf < 8; nf++)
                    mma16816(acc[mf][nf], ah,
                             bh[nf >> 1][(nf & 1) * 2], bh[nf >> 1][(nf & 1) * 2 + 1]);
#pragma unroll
                for (int nf = 0; nf < 8; nf++)
                    mma16816(acc[mf][nf], ah,
                             bl[nf >> 1][(nf & 1) * 2], bl[nf >> 1][(nf & 1) * 2 + 1]);
#pragma unroll
                for (int nf = 0; nf < 8; nf++)
                    mma16816(acc[mf][nf], al,
                             bh[nf >> 1][(nf & 1) * 2], bh[nf >> 1][(nf & 1) * 2 + 1]);
            }
        }
        __syncthreads();
        buf = (buf + 1) % 3;
    }

    // ---- epilogue: tril mask + store (float2) ----
#pragma unroll
    for (int mf = 0; mf < 4; mf++) {
        const int r0 = rowBase + wr * 64 + mf * 16 + (lane >> 2);
        const int r1 = r0 + 8;
#pragma unroll
        for (int nf = 0; nf < 8; nf++) {
            const int c0 = colBase + wc * 64 + nf * 8 + (lane & 3) * 2;
            const float* a4 = acc[mf][nf];
            float2 v0, v1;
            v0.x = (r0 >= c0 + 0) ? a4[0] : 0.0f;
            v0.y = (r0 >= c0 + 1) ? a4[1] : 0.0f;
            v1.x = (r1 >= c0 + 0) ? a4[2] : 0.0f;
            v1.y = (r1 >= c0 + 1) ? a4[3] : 0.0f;
            *reinterpret_cast<float2*>(&C[(size_t)r0 * N4K + c0]) = v0;
            *reinterpret_cast<float2*>(&C[(size_t)r1 * N4K + c0]) = v1;
        }
    }
}

// ---------------- launch ----------------
extern "C" void kernel_launch(void* const* d_in, const int* in_sizes, int n_in,
                              void* d_out, int out_size) {
    const float* A = (const float*)d_in[0];
    const float* B = (const float*)d_in[1];
    float* C = (float*)d_out;

    // Unconditional (no static guard): idempotent, identical on every call.
    cudaFuncSetAttribute(trilmm_mma2,
                         cudaFuncAttributeMaxDynamicSharedMemorySize, SMEM_SZ);

    conv_a<<<16384, 256>>>(A);
    conv_b<<<dim3(128, 128), 256>>>(B);
    zero_upper<<<dim3(32, 32), 256>>>(C);
    trilmm_mma2<<<272, 256, SMEM_SZ>>>(C);
}

// round 16
// speedup vs baseline: 2.9637x; 2.9637x over previous
#include <cuda_runtime.h>
#include <cuda_fp16.h>
#include <cstdint>

#define N4K 4096

// ---------------- device scratch (allocation-free) ----------------
__device__ __half g_Ah[(size_t)N4K * N4K];   // masked tril(A), fp16, [M,K]
__device__ __half g_Bt[(size_t)N4K * N4K];   // masked tril(B) transposed, fp16, [N,K]

// ---------------- helpers ----------------
__device__ __forceinline__ uint32_t smem_u32(const void* p) {
    uint32_t a;
    asm("{ .reg .u64 t; cvta.to.shared.u64 t, %1; cvt.u32.u64 %0, t; }"
        : "=r"(a) : "l"(p));
    return a;
}

__device__ __forceinline__ void ldsm4(uint32_t* r, uint32_t addr) {
    asm volatile("ldmatrix.sync.aligned.m8n8.x4.shared.b16 {%0,%1,%2,%3}, [%4];"
        : "=r"(r[0]), "=r"(r[1]), "=r"(r[2]), "=r"(r[3]) : "r"(addr));
}

__device__ __forceinline__ void mma16816(float* c, const uint32_t* a,
                                         uint32_t b0, uint32_t b1) {
    asm volatile(
        "mma.sync.aligned.m16n8k16.row.col.f32.f16.f16.f32 "
        "{%0,%1,%2,%3},{%4,%5,%6,%7},{%8,%9},{%0,%1,%2,%3};"
        : "+f"(c[0]), "+f"(c[1]), "+f"(c[2]), "+f"(c[3])
        : "r"(a[0]), "r"(a[1]), "r"(a[2]), "r"(a[3]), "r"(b0), "r"(b1));
}

__device__ __forceinline__ void cpasync16(uint32_t saddr, const void* g) {
    asm volatile("cp.async.cg.shared.global [%0], [%1], 16;"
        :: "r"(saddr), "l"(g));
}

// ---------------- conversion kernels ----------------
__global__ void __launch_bounds__(256) conv_a(const float* __restrict__ A) {
    size_t t = (size_t)blockIdx.x * 256 + threadIdx.x;   // float4 index
    int i  = (int)(t >> 10);          // row
    int c4 = (int)(t & 1023) << 2;    // col start
    float4 v = *reinterpret_cast<const float4*>(A + (size_t)i * N4K + c4);
    float a0 = (c4 + 0 <= i) ? v.x : 0.0f;
    float a1 = (c4 + 1 <= i) ? v.y : 0.0f;
    float a2 = (c4 + 2 <= i) ? v.z : 0.0f;
    float a3 = (c4 + 3 <= i) ? v.w : 0.0f;
    __half h0 = __float2half(a0), h1 = __float2half(a1);
    __half h2 = __float2half(a2), h3 = __float2half(a3);
    uint2 u;
    u.x = (uint32_t)__half_as_ushort(h0) | ((uint32_t)__half_as_ushort(h1) << 16);
    u.y = (uint32_t)__half_as_ushort(h2) | ((uint32_t)__half_as_ushort(h3) << 16);
    *reinterpret_cast<uint2*>(&g_Ah[(size_t)i * N4K + c4]) = u;
}

// B: transpose + mask(tril: keep k >= j) -> Bt[j][k], fp16
__global__ void __launch_bounds__(256) conv_b(const float* __restrict__ B) {
    __shared__ float tile[32][33];
    int j0 = blockIdx.x * 32, k0 = blockIdx.y * 32;
    int tx = threadIdx.x & 31, ty = threadIdx.x >> 5;   // ty 0..7
#pragma unroll
    for (int yy = 0; yy < 4; yy++) {
        int k = k0 + ty + yy * 8;
        int j = j0 + tx;
        float v = B[(size_t)k * N4K + j];
        if (k < j) v = 0.0f;
        tile[ty + yy * 8][tx] = v;
    }
    __syncthreads();
#pragma unroll
    for (int yy = 0; yy < 4; yy++) {
        int j = j0 + ty + yy * 8;
        int k = k0 + tx;
        g_Bt[(size_t)j * N4K + k] = __float2half(tile[tx][ty + yy * 8]);
    }
}

// ---------------- zero upper triangle tiles ----------------
__global__ void __launch_bounds__(256) zero_upper(float* __restrict__ C) {
    int bj = blockIdx.x, bi = blockIdx.y;
    if (bi >= bj) return;
    int rowBase = bi * 128, colBase = bj * 128;
    float4 z = make_float4(0.f, 0.f, 0.f, 0.f);
#pragma unroll
    for (int it = 0; it < 16; it++) {
        int idx = threadIdx.x + it * 256;       // float4 index in 128x32
        int r = idx >> 5, c4 = (idx & 31) << 2;
        *reinterpret_cast<float4*>(&C[(size_t)(rowBase + r) * N4K + colBase + c4]) = z;
    }
}

// ---------------- main warp-MMA GEMM: CTA 128x128, warp 64x32, BK=64 -----------
// SMEM per stage: A 128 rows x 128B (64 fp16, SW128 XOR) = 16KB, B same = 16KB.
#define B_OFF    16384
#define STAGE_B  32768
#define SMEM_SZ  (2 * STAGE_B)          // 65536

__device__ __forceinline__ void load_stage(uint32_t sbase, int buf, int k0,
                                           int rowBase, int colBase, int tid,
                                           bool valid) {
    if (valid) {
        const uint32_t sb = sbase + buf * STAGE_B;
        const int r  = tid >> 1;            // 0..127
        const int cg = (tid & 1) * 4;       // chunk base 0 or 4 (16B chunks)
        const uint32_t xm = (uint32_t)((r & 7) << 4);
        const __half* pa = g_Ah + (size_t)(rowBase + r) * N4K + k0;
        const __half* pb = g_Bt + (size_t)(colBase + r) * N4K + k0;
        const uint32_t dstA = sb + (uint32_t)(r * 128);
        const uint32_t dstB = dstA + B_OFF;
#pragma unroll
        for (int i = 0; i < 4; i++)
            cpasync16(dstA + (((uint32_t)((cg + i) * 16)) ^ xm), pa + (cg + i) * 8);
#pragma unroll
        for (int i = 0; i < 4; i++)
            cpasync16(dstB + (((uint32_t)((cg + i) * 16)) ^ xm), pb + (cg + i) * 8);
    }
    asm volatile("cp.async.commit_group;" ::: "memory");
}

__global__ void __launch_bounds__(256)
trilmm_fp16(float* __restrict__ C) {
    extern __shared__ char smem[];
    const uint32_t sbase = smem_u32(smem);
    const int tid  = threadIdx.x;
    const int wid  = tid >> 5;
    const int lane = tid & 31;
    const int wr = wid >> 2;            // 0..1  -> m offset wr*64
    const int wc = wid & 3;             // 0..3  -> n offset wc*32

    // diagonal-major block mapping (largest work first)
    int rem = blockIdx.x, cnt = 1, d = 31;
    while (rem >= cnt) { rem -= cnt; d--; cnt++; }
    const int bj = rem, bi = bj + d;
    const int rowBase = bi * 128, colBase = bj * 128;
    const int nStages = (d + 1) * 2;    // K chunks of 64

    float acc[4][4][4];
#pragma unroll
    for (int i = 0; i < 4; i++)
#pragma unroll
        for (int j = 0; j < 4; j++)
#pragma unroll
            for (int k = 0; k < 4; k++) acc[i][j][k] = 0.0f;

    // lane-invariant ldmatrix address parts (XOR-SW128, 128B rows)
    const uint32_t xm  = (uint32_t)((lane & 7) << 4);
    const uint32_t pAo = (uint32_t)((wr * 64 + (lane & 15)) * 128);
    const uint32_t aKo = (uint32_t)((lane >> 4) * 16);
    const uint32_t pBo = (uint32_t)((wc * 32 + ((lane >> 4) & 1) * 8 + (lane & 7)) * 128);
    const uint32_t bKo = (uint32_t)((lane & 8) * 2);

    load_stage(sbase, 0, colBase, rowBase, colBase, tid, true);

    for (int s = 0; s < nStages; s++) {
        load_stage(sbase, (s + 1) & 1, colBase + (s + 1) * 64,
                   rowBase, colBase, tid, (s + 1) < nStages);
        asm volatile("cp.async.wait_group 1;" ::: "memory");
        __syncthreads();

        const uint32_t stA = sbase + (s & 1) * STAGE_B;
        const uint32_t stB = stA + B_OFF;

#pragma unroll
        for (int ks = 0; ks < 4; ks++) {
            const uint32_t kc = (uint32_t)(ks * 32);   // 16 halves = 32 bytes
            uint32_t bh[2][4];
            ldsm4(bh[0], stB + pBo + 0 * 16 * 128 + ((kc + bKo) ^ xm));
            ldsm4(bh[1], stB + pBo + 1 * 16 * 128 + ((kc + bKo) ^ xm));
#pragma unroll
            for (int mf = 0; mf < 4; mf++) {
                uint32_t ah[4];
                ldsm4(ah, stA + pAo + mf * 16 * 128 + ((kc + aKo) ^ xm));
#pragma unroll
                for (int nf = 0; nf < 4; nf++)
                    mma16816(acc[mf][nf], ah,
                             bh[nf >> 1][(nf & 1) * 2], bh[nf >> 1][(nf & 1) * 2 + 1]);
            }
        }
        __syncthreads();
    }

    // ---- epilogue: tril mask + store (float2) ----
#pragma unroll
    for (int mf = 0; mf < 4; mf++) {
        const int r0 = rowBase + wr * 64 + mf * 16 + (lane >> 2);
        const int r1 = r0 + 8;
#pragma unroll
        for (int nf = 0; nf < 4; nf++) {
            const int c0 = colBase + wc * 32 + nf * 8 + (lane & 3) * 2;
            const float* a4 = acc[mf][nf];
            float2 v0, v1;
            v0.x = (r0 >= c0 + 0) ? a4[0] : 0.0f;
            v0.y = (r0 >= c0 + 1) ? a4[1] : 0.0f;
            v1.x = (r1 >= c0 + 0) ? a4[2] : 0.0f;
            v1.y = (r1 >= c0 + 1) ? a4[3] : 0.0f;
            *reinterpret_cast<float2*>(&C[(size_t)r0 * N4K + c0]) = v0;
            *reinterpret_cast<float2*>(&C[(size_t)r1 * N4K + c0]) = v1;
        }
    }
}

// ---------------- launch ----------------
extern "C" void kernel_launch(void* const* d_in, const int* in_sizes, int n_in,
                              void* d_out, int out_size) {
    const float* A = (const float*)d_in[0];
    const float* B = (const float*)d_in[1];
    float* C = (float*)d_out;

    cudaFuncSetAttribute(trilmm_fp16,
                         cudaFuncAttributeMaxDynamicSharedMemorySize, SMEM_SZ);

    conv_a<<<16384, 256>>>(A);
    conv_b<<<dim3(128, 128), 256>>>(B);
    zero_upper<<<dim3(32, 32), 256>>>(C);
    trilmm_fp16<<<528, 256, SMEM_SZ>>>(C);
}